// round 1
// baseline (speedup 1.0000x reference)
#include <cuda_runtime.h>
#include <math.h>

#define BB 128
#define TT 512
#define II 256
#define HH 1024
#define GG 4096
#define CC 1000

// Scratch: h ping-pong + cell state. Static device globals (no dynamic alloc).
__device__ float g_h[2][BB * HH];
__device__ float g_c[BB * HH];

__global__ void zero_hc() {
    int i = blockIdx.x * blockDim.x + threadIdx.x;
    if (i < BB * HH) { g_h[0][i] = 0.f; g_c[i] = 0.f; }
}

// One LSTM timestep, fully fused:
//   gates[128 x 4096] = [x_t | h_{t-1}] @ [W_ih | W_hh]^T + b_ih + b_hh
//   then thread-local cell update (each thread owns all 4 gates of its h-cols).
// Grid: 128 CTAs, each owns 8 h-columns (=> 32 gate columns). Block: 256 threads.
// Thread (ty=tid>>3 in [0,32), tx=tid&7): 4 batch rows (ty*4..+3) x 1 h-col (tx),
// with the 4 gate columns of that h-col -> acc[4][4].
__global__ __launch_bounds__(256) void lstm_step(
    const float* __restrict__ x,
    const float* __restrict__ Wih,
    const float* __restrict__ Whh,
    const float* __restrict__ bih,
    const float* __restrict__ bhh,
    int t)
{
    __shared__ float As[128][33];  // [m][kk], pad 33 to kill LDS bank conflicts
    __shared__ float Bs[32][33];   // [j][kk], j = n_local*4 + gate_q

    const float* __restrict__ h_in = g_h[t & 1];
    float* __restrict__ h_out      = g_h[(t + 1) & 1];

    const int tid   = threadIdx.x;
    const int ty    = tid >> 3;   // 0..31
    const int tx    = tid & 7;    // 0..7
    const int nbase = blockIdx.x * 8;

    float acc[4][4];
#pragma unroll
    for (int r = 0; r < 4; r++)
#pragma unroll
        for (int q = 0; q < 4; q++) acc[r][q] = 0.f;

    // ---------------- Phase 1: x contribution (K = 256, 8 chunks of 32) -----
    const float* xrow_base = x + (size_t)t * II;  // x[m][t][k] = x[m*T*I + t*I + k]
#pragma unroll 1
    for (int kc = 0; kc < 8; kc++) {
        const int k0 = kc * 32;
        // Load A tile: 128 rows x 32 cols = 1024 float4-quads -> 4 per thread
        for (int v = tid; v < 1024; v += 256) {
            int m  = v >> 3;
            int kv = v & 7;
            float4 val = *reinterpret_cast<const float4*>(
                xrow_base + (size_t)m * (TT * II) + k0 + kv * 4);
            As[m][kv * 4 + 0] = val.x;
            As[m][kv * 4 + 1] = val.y;
            As[m][kv * 4 + 2] = val.z;
            As[m][kv * 4 + 3] = val.w;
        }
        // Load B tile: 32 gate rows x 32 cols = 256 float4 -> 1 per thread
        {
            int j  = tid >> 3;   // 0..31
            int kv = tid & 7;
            int row = (j & 3) * HH + nbase + (j >> 2);  // q*H + n
            float4 val = *reinterpret_cast<const float4*>(
                Wih + (size_t)row * II + k0 + kv * 4);
            Bs[j][kv * 4 + 0] = val.x;
            Bs[j][kv * 4 + 1] = val.y;
            Bs[j][kv * 4 + 2] = val.z;
            Bs[j][kv * 4 + 3] = val.w;
        }
        __syncthreads();
#pragma unroll 8
        for (int kk = 0; kk < 32; kk++) {
            float a[4], b[4];
#pragma unroll
            for (int r = 0; r < 4; r++) a[r] = As[ty * 4 + r][kk];
#pragma unroll
            for (int q = 0; q < 4; q++) b[q] = Bs[tx * 4 + q][kk];
#pragma unroll
            for (int r = 0; r < 4; r++)
#pragma unroll
                for (int q = 0; q < 4; q++) acc[r][q] += a[r] * b[q];
        }
        __syncthreads();
    }

    // ---------------- Phase 2: h contribution (K = 1024, 32 chunks of 32) ---
#pragma unroll 1
    for (int kc = 0; kc < 32; kc++) {
        const int k0 = kc * 32;
        for (int v = tid; v < 1024; v += 256) {
            int m  = v >> 3;
            int kv = v & 7;
            float4 val = *reinterpret_cast<const float4*>(
                h_in + (size_t)m * HH + k0 + kv * 4);
            As[m][kv * 4 + 0] = val.x;
            As[m][kv * 4 + 1] = val.y;
            As[m][kv * 4 + 2] = val.z;
            As[m][kv * 4 + 3] = val.w;
        }
        {
            int j  = tid >> 3;
            int kv = tid & 7;
            int row = (j & 3) * HH + nbase + (j >> 2);
            float4 val = *reinterpret_cast<const float4*>(
                Whh + (size_t)row * HH + k0 + kv * 4);
            Bs[j][kv * 4 + 0] = val.x;
            Bs[j][kv * 4 + 1] = val.y;
            Bs[j][kv * 4 + 2] = val.z;
            Bs[j][kv * 4 + 3] = val.w;
        }
        __syncthreads();
#pragma unroll 8
        for (int kk = 0; kk < 32; kk++) {
            float a[4], b[4];
#pragma unroll
            for (int r = 0; r < 4; r++) a[r] = As[ty * 4 + r][kk];
#pragma unroll
            for (int q = 0; q < 4; q++) b[q] = Bs[tx * 4 + q][kk];
#pragma unroll
            for (int r = 0; r < 4; r++)
#pragma unroll
                for (int q = 0; q < 4; q++) acc[r][q] += a[r] * b[q];
        }
        __syncthreads();
    }

    // ---------------- Epilogue: LSTM cell update (thread-local) -------------
    const int n = nbase + tx;
    const float bi = bih[0 * HH + n] + bhh[0 * HH + n];
    const float bf = bih[1 * HH + n] + bhh[1 * HH + n];
    const float bg = bih[2 * HH + n] + bhh[2 * HH + n];
    const float bo = bih[3 * HH + n] + bhh[3 * HH + n];
#pragma unroll
    for (int r = 0; r < 4; r++) {
        int m   = ty * 4 + r;
        int idx = m * HH + n;
        float gi = acc[r][0] + bi;
        float gf = acc[r][1] + bf;
        float gg = acc[r][2] + bg;
        float go = acc[r][3] + bo;
        float iv = 1.f / (1.f + expf(-gi));
        float fv = 1.f / (1.f + expf(-gf));
        float gv = tanhf(gg);
        float ov = 1.f / (1.f + expf(-go));
        float cn = fv * g_c[idx] + iv * gv;
        g_c[idx]   = cn;
        h_out[idx] = ov * tanhf(cn);
    }
}

// Final FC: out[b][c] = h[b,:] . fc_W[c,:] + fc_b[c]. One warp per output.
__global__ __launch_bounds__(256) void fc_kernel(
    const float* __restrict__ fcW,
    const float* __restrict__ fcb,
    float* __restrict__ out)
{
    int w    = blockIdx.x * 8 + (threadIdx.x >> 5);
    int lane = threadIdx.x & 31;
    if (w >= BB * CC) return;
    int b = w / CC;
    int c = w % CC;
    const float* __restrict__ h  = g_h[0] + b * HH;  // final h lives in buffer 0
    const float* __restrict__ wr = fcW + (size_t)c * HH;
    float s = 0.f;
#pragma unroll 4
    for (int k = lane; k < HH; k += 32) s += h[k] * wr[k];
#pragma unroll
    for (int o = 16; o; o >>= 1) s += __shfl_down_sync(0xFFFFFFFFu, s, o);
    if (lane == 0) out[b * CC + c] = s + fcb[c];
}

extern "C" void kernel_launch(void* const* d_in, const int* in_sizes, int n_in,
                              void* d_out, int out_size)
{
    const float* x   = (const float*)d_in[0];
    const float* Wih = (const float*)d_in[1];
    const float* Whh = (const float*)d_in[2];
    const float* bih = (const float*)d_in[3];
    const float* bhh = (const float*)d_in[4];
    const float* fcW = (const float*)d_in[5];
    const float* fcb = (const float*)d_in[6];
    float* out = (float*)d_out;

    zero_hc<<<(BB * HH + 255) / 256, 256>>>();
    for (int t = 0; t < TT; t++)
        lstm_step<<<128, 256>>>(x, Wih, Whh, bih, bhh, t);
    fc_kernel<<<(BB * CC + 7) / 8, 256>>>(fcW, fcb, out);
}

// round 3
// speedup vs baseline: 4.7791x; 4.7791x over previous
#include <cuda_runtime.h>
#include <cuda_bf16.h>
#include <cstdint>
#include <math.h>

#define BB 128
#define TT 512
#define II 256
#define HH 1024
#define GG 4096
#define CC 1000
#define KTOT 1280
#define NCHUNK 20

// SMEM: per buffer Ahi 8K | Alo 8K | Bhi 8K | Blo 8K = 32K, double buffered
#define BUF_STRIDE 32768
#define SMEM_DYN (2 * BUF_STRIDE + 1024)

// ---------------- scratch (static device globals; no dynamic alloc) ----------
__device__ __align__(16) __nv_bfloat16 g_Wh[GG * KTOT];    // weights hi, permuted rows
__device__ __align__(16) __nv_bfloat16 g_Wl[GG * KTOT];    // weights lo
__device__ __align__(16) __nv_bfloat16 g_xh[TT * BB * II]; // x hi, [t][m][k]
__device__ __align__(16) __nv_bfloat16 g_xl[TT * BB * II];
__device__ __align__(16) __nv_bfloat16 g_hh[2][BB * HH];   // h hi ping-pong
__device__ __align__(16) __nv_bfloat16 g_hl[2][BB * HH];   // h lo ping-pong
__device__ float g_c[BB * HH];
__device__ float g_bs[GG];                                 // b_ih + b_hh, original order

// ---------------- helpers -----------------------------------------------------
__device__ __forceinline__ uint32_t smem_u32(const void* p) {
    uint32_t a;
    asm("{ .reg .u64 t; cvta.to.shared.u64 t, %1; cvt.u32.u64 %0, t; }" : "=r"(a) : "l"(p));
    return a;
}
__device__ __forceinline__ void cp16(uint32_t saddr, const void* gaddr) {
    asm volatile("cp.async.cg.shared.global [%0], [%1], 16;" :: "r"(saddr), "l"(gaddr) : "memory");
}
__device__ __forceinline__ void ldsm4(uint32_t addr, uint32_t& r0, uint32_t& r1,
                                      uint32_t& r2, uint32_t& r3) {
    asm volatile("ldmatrix.sync.aligned.m8n8.x4.shared.b16 {%0,%1,%2,%3}, [%4];"
                 : "=r"(r0), "=r"(r1), "=r"(r2), "=r"(r3) : "r"(addr));
}
__device__ __forceinline__ void mma16816(float* c, const uint32_t* a, uint32_t b0, uint32_t b1) {
    asm volatile(
        "mma.sync.aligned.m16n8k16.row.col.f32.bf16.bf16.f32 "
        "{%0,%1,%2,%3}, {%4,%5,%6,%7}, {%8,%9}, {%0,%1,%2,%3};"
        : "+f"(c[0]), "+f"(c[1]), "+f"(c[2]), "+f"(c[3])
        : "r"(a[0]), "r"(a[1]), "r"(a[2]), "r"(a[3]), "r"(b0), "r"(b1));
}

// ---------------- prep kernels -----------------------------------------------
// W rows permuted: stored row r = nb*64 + hc*4 + q  <->  original row q*H + nb*16 + hc.
// K dim concatenates [W_ih | W_hh].
__global__ void prep_w(const float* __restrict__ Wih, const float* __restrict__ Whh) {
    int idx = blockIdx.x * blockDim.x + threadIdx.x;
    if (idx >= GG * KTOT) return;
    int r = idx / KTOT, k = idx - r * KTOT;
    int nb = r >> 6, j = r & 63, hc = j >> 2, q = j & 3;
    int orig = q * HH + nb * 16 + hc;
    float v = (k < II) ? Wih[(size_t)orig * II + k] : Whh[(size_t)orig * HH + (k - II)];
    __nv_bfloat16 hi = __float2bfloat16(v);
    g_Wh[idx] = hi;
    g_Wl[idx] = __float2bfloat16(v - __bfloat162float(hi));
}

__global__ void prep_x(const float* __restrict__ x) {
    int idx = blockIdx.x * blockDim.x + threadIdx.x;
    if (idx >= TT * BB * II) return;
    int t = idx / (BB * II);
    int rem = idx - t * (BB * II);
    int m = rem / II, k = rem - m * II;
    float v = x[((size_t)m * TT + t) * II + k];
    __nv_bfloat16 hi = __float2bfloat16(v);
    g_xh[idx] = hi;
    g_xl[idx] = __float2bfloat16(v - __bfloat162float(hi));
}

__global__ void prep_misc(const float* __restrict__ bih, const float* __restrict__ bhh) {
    int i = blockIdx.x * blockDim.x + threadIdx.x;
    if (i < BB * HH) {
        g_hh[0][i] = __float2bfloat16(0.f);
        g_hl[0][i] = __float2bfloat16(0.f);
        g_c[i] = 0.f;
    }
    if (i < GG) g_bs[i] = bih[i] + bhh[i];
}

// ---------------- per-step: gates GEMM (HMMA bf16x3) + LSTM update -----------
// Grid: (64 n-tiles, 2 m-halves). Block 256 = 8 warps (4m x 2n), warp tile 16x32.
// CTA tile: M=64 (batch rows by*64..), N=64 gate cols (= 16 h-cols x 4 gates).
__global__ __launch_bounds__(256, 1) void lstm_step_hmma(int t) {
    extern __shared__ __align__(16) char dsm[];
    const uint32_t dbase = (smem_u32(dsm) + 1023) & ~1023u;

    const int tid = threadIdx.x;
    const int wid = tid >> 5;
    const int lid = tid & 31;
    const int wm = wid & 3;       // warp m-tile (16 rows each)
    const int wn = wid >> 2;      // warp n-tile (32 cols each)
    const int bx = blockIdx.x;    // n block (64 gate cols)
    const int by = blockIdx.y;    // m half (64 rows)

    const __nv_bfloat16* __restrict__ hsrc_h = g_hh[t & 1];
    const __nv_bfloat16* __restrict__ hsrc_l = g_hl[t & 1];
    const size_t xoff = (size_t)t * (BB * II) + (size_t)(by * 64) * II;
    const size_t hoff = (size_t)(by * 64) * HH;
    const size_t woff = (size_t)(bx * 64) * KTOT;

    float acc[4][4];
#pragma unroll
    for (int nf = 0; nf < 4; nf++)
#pragma unroll
        for (int i = 0; i < 4; i++) acc[nf][i] = 0.f;

    // -------- async loader for one chunk into buffer buf ----------------------
    auto load_chunk = [&](int kc) {
        const uint32_t bofs = (kc & 1) ? (uint32_t)BUF_STRIDE : 0u;
        const int k0 = kc * 64;
        const bool xreg = (k0 < II);
#pragma unroll
        for (int s = 0; s < 8; s++) {
            int idx = tid + 256 * s;          // 0..2047
            int region = idx >> 9;            // 0 Ahi, 1 Alo, 2 Bhi, 3 Blo
            int within = idx & 511;
            int row = within >> 3, seg = within & 7;
            uint32_t saddr = dbase + bofs + (uint32_t)region * 8192u
                           + (uint32_t)row * 128u + (uint32_t)((seg ^ (row & 7)) << 4);
            const __nv_bfloat16* g;
            if (region < 2) {
                if (xreg) {
                    size_t o = xoff + (size_t)row * II + (k0 + seg * 8);
                    g = (region == 0 ? g_xh : g_xl) + o;
                } else {
                    size_t o = hoff + (size_t)row * HH + (k0 - II + seg * 8);
                    g = (region == 0 ? hsrc_h : hsrc_l) + o;
                }
            } else {
                size_t o = woff + (size_t)row * KTOT + (k0 + seg * 8);
                g = (region == 2 ? g_Wh : g_Wl) + o;
            }
            cp16(saddr, g);
        }
        asm volatile("cp.async.commit_group;" ::: "memory");
    };

    load_chunk(0);

#pragma unroll 1
    for (int kc = 0; kc < NCHUNK; kc++) {
        if (kc + 1 < NCHUNK) {
            load_chunk(kc + 1);
            asm volatile("cp.async.wait_group 1;" ::: "memory");
        } else {
            asm volatile("cp.async.wait_group 0;" ::: "memory");
        }
        __syncthreads();

        const uint32_t bofs = (kc & 1) ? (uint32_t)BUF_STRIDE : 0u;
        const uint32_t a_h = dbase + bofs;
        const uint32_t b_h = a_h + 16384u;

        // lane-fixed pieces of ldmatrix addressing
        const int mi = lid >> 3, lr = lid & 7;
        const int arow = wm * 16 + ((mi & 1) << 3) + lr;     // A row for x4 load
        const uint32_t aoff = (uint32_t)arow * 128u;
        const int axor = arow & 7;

#pragma unroll
        for (int ks = 0; ks < 4; ks++) {
            uint32_t ah[4], al[4];
            {
                int kb = ks * 2 + (mi >> 1);
                uint32_t ad = a_h + aoff + (uint32_t)((kb ^ axor) << 4);
                ldsm4(ad, ah[0], ah[1], ah[2], ah[3]);
                ldsm4(ad + 8192u, al[0], al[1], al[2], al[3]);
            }
            uint32_t bh[8], bl[8];
#pragma unroll
            for (int g = 0; g < 2; g++) {                    // nf pair {0,1} / {2,3}
                int brow = wn * 32 + (g * 2 + (mi >> 1)) * 8 + lr;
                int kb = ks * 2 + (mi & 1);
                uint32_t bd = b_h + (uint32_t)brow * 128u + (uint32_t)((kb ^ (brow & 7)) << 4);
                ldsm4(bd, bh[g * 4 + 0], bh[g * 4 + 1], bh[g * 4 + 2], bh[g * 4 + 3]);
                ldsm4(bd + 8192u, bl[g * 4 + 0], bl[g * 4 + 1], bl[g * 4 + 2], bl[g * 4 + 3]);
            }
#pragma unroll
            for (int nf = 0; nf < 4; nf++) {
                mma16816(acc[nf], ah, bh[nf * 2], bh[nf * 2 + 1]);   // hi*hi
                mma16816(acc[nf], ah, bl[nf * 2], bl[nf * 2 + 1]);   // hi*lo
                mma16816(acc[nf], al, bh[nf * 2], bh[nf * 2 + 1]);   // lo*hi
            }
        }
        __syncthreads();
    }

    // -------- epilogue: bias + LSTM cell update -------------------------------
    // Fragment cols: lane quad lq = lid&3 -> cols lq*2, lq*2+1.
    // Gate-interleaved cols: even quad = (i,f) of h-col, odd quad = (g,o).
    const int lq = lid & 3;
    const bool hasIF = (lq & 1) == 0;
    const int hcl = lq >> 1;
    const int rbase = by * 64 + wm * 16 + (lid >> 2);
    float* __restrict__ cptr = g_c;
    __nv_bfloat16* __restrict__ hh_o = g_hh[(t + 1) & 1];
    __nv_bfloat16* __restrict__ hl_o = g_hl[(t + 1) & 1];

#pragma unroll
    for (int nf = 0; nf < 4; nf++) {
        const int nglob = bx * 16 + wn * 8 + nf * 2 + hcl;   // h-col index
        const float bias0 = g_bs[(hasIF ? 0 : 2) * HH + nglob];
        const float bias1 = g_bs[(hasIF ? 1 : 3) * HH + nglob];
        float d0 = acc[nf][0] + bias0;
        float d1 = acc[nf][1] + bias1;
        float d2 = acc[nf][2] + bias0;
        float d3 = acc[nf][3] + bias1;
        float e0 = __shfl_xor_sync(0xFFFFFFFFu, d0, 1);
        float e1 = __shfl_xor_sync(0xFFFFFFFFu, d1, 1);
        float e2 = __shfl_xor_sync(0xFFFFFFFFu, d2, 1);
        float e3 = __shfl_xor_sync(0xFFFFFFFFu, d3, 1);
        if (hasIF) {
#pragma unroll
            for (int r = 0; r < 2; r++) {
                float gi = r ? d2 : d0, gf = r ? d3 : d1;
                float gg = r ? e2 : e0, go = r ? e3 : e1;
                float iv = 1.f / (1.f + expf(-gi));
                float fv = 1.f / (1.f + expf(-gf));
                float gv = tanhf(gg);
                float ov = 1.f / (1.f + expf(-go));
                size_t idx = (size_t)(rbase + r * 8) * HH + nglob;
                float cn = fv * cptr[idx] + iv * gv;
                cptr[idx] = cn;
                float hv = ov * tanhf(cn);
                __nv_bfloat16 hi = __float2bfloat16(hv);
                hh_o[idx] = hi;
                hl_o[idx] = __float2bfloat16(hv - __bfloat162float(hi));
            }
        }
    }
}

// ---------------- final FC ----------------------------------------------------
__global__ __launch_bounds__(256) void fc_kernel(
    const float* __restrict__ fcW, const float* __restrict__ fcb, float* __restrict__ out) {
    int w = blockIdx.x * 8 + (threadIdx.x >> 5);
    int lane = threadIdx.x & 31;
    if (w >= BB * CC) return;
    int b = w / CC, c = w - b * CC;
    const __nv_bfloat16* __restrict__ hh = g_hh[0] + (size_t)b * HH;
    const __nv_bfloat16* __restrict__ hl = g_hl[0] + (size_t)b * HH;
    const float* __restrict__ wr = fcW + (size_t)c * HH;
    float s = 0.f;
#pragma unroll 4
    for (int k = lane; k < HH; k += 32)
        s += (__bfloat162float(hh[k]) + __bfloat162float(hl[k])) * wr[k];
#pragma unroll
    for (int o = 16; o; o >>= 1) s += __shfl_down_sync(0xFFFFFFFFu, s, o);
    if (lane == 0) out[b * CC + c] = s + fcb[c];
}

extern "C" void kernel_launch(void* const* d_in, const int* in_sizes, int n_in,
                              void* d_out, int out_size) {
    const float* x   = (const float*)d_in[0];
    const float* Wih = (const float*)d_in[1];
    const float* Whh = (const float*)d_in[2];
    const float* bih = (const float*)d_in[3];
    const float* bhh = (const float*)d_in[4];
    const float* fcW = (const float*)d_in[5];
    const float* fcb = (const float*)d_in[6];
    float* out = (float*)d_out;

    cudaFuncSetAttribute(lstm_step_hmma, cudaFuncAttributeMaxDynamicSharedMemorySize, SMEM_DYN);

    prep_w<<<(GG * KTOT + 255) / 256, 256>>>(Wih, Whh);
    prep_x<<<(TT * BB * II + 255) / 256, 256>>>(x);
    prep_misc<<<(BB * HH + 255) / 256, 256>>>(bih, bhh);
    for (int t = 0; t < TT; t++)
        lstm_step_hmma<<<dim3(64, 2, 1), 256, SMEM_DYN>>>(t);
    fc_kernel<<<(BB * CC + 7) / 8, 256>>>(fcW, fcb, out);
}